// round 16
// baseline (speedup 1.0000x reference)
#include <cuda_runtime.h>
#include <cuda_fp16.h>
#include <cstdint>

// Problem constants
#define BATCH 16
#define CDIM  768
#define NTOK  4096
#define HEADS 12
#define DHEAD 64

// ---------------------------------------------------------------------------
// Scratch (__device__ globals; no cudaMalloc allowed)
// ---------------------------------------------------------------------------
__device__ __half g_w16T[(size_t)BATCH * NTOK * CDIM];      // w fp16, [b][n][c]
__device__ float g_inv2[BATCH * CDIM];
__device__ float g_attn[BATCH * CDIM];
__device__ float g_PiSum[BATCH * HEADS];
__device__ float g_rnPart[(size_t)BATCH * CDIM * 32];       // rownorm partials [row][nBlk]
__device__ float g_dotsP[(size_t)BATCH * 128 * CDIM];       // dots partials [b][blk][co]
__device__ float g_PiP[(size_t)BATCH * 128 * HEADS];        // Pi-sum partials [b][blk][h]
__device__ __half g_A16[CDIM * CDIM];                       // W_qkv fp16, [m][k]
__device__ __half g_A2[(size_t)BATCH * CDIM * CDIM];        // W_out*attn fp16, [b][m][k]
__device__ __half g_B16[(size_t)BATCH * NTOK * CDIM];       // B operand fp16, [b][n][k]

// ---------------------------------------------------------------------------
// PTX helpers (baseline sm_80+ features only: cp.async, ldmatrix, mma.sync)
// ---------------------------------------------------------------------------
__device__ __forceinline__ uint32_t smem_to_u32(const void* p) {
    uint32_t a;
    asm("{ .reg .u64 t; cvta.to.shared.u64 t, %1; cvt.u32.u64 %0, t; }" : "=r"(a) : "l"(p));
    return a;
}
#define CP_ASYNC16(dst, src) asm volatile( \
    "cp.async.cg.shared.global [%0], [%1], 16;" :: "r"(dst), "l"(src) : "memory")
#define CP_COMMIT() asm volatile("cp.async.commit_group;" ::: "memory")
template <int N>
__device__ __forceinline__ void cp_wait_group() {
    asm volatile("cp.async.wait_group %0;" :: "n"(N) : "memory");
}
#define LDSM4(r0, r1, r2, r3, addr) asm volatile( \
    "ldmatrix.sync.aligned.m8n8.x4.shared.b16 {%0,%1,%2,%3}, [%4];" \
    : "=r"(r0), "=r"(r1), "=r"(r2), "=r"(r3) : "r"(addr))

__device__ __forceinline__ void mma16816h(float* c, const uint32_t* a, const uint32_t* b) {
    asm volatile(
        "mma.sync.aligned.m16n8k16.row.col.f32.f16.f16.f32 "
        "{%0,%1,%2,%3}, {%4,%5,%6,%7}, {%8,%9}, {%0,%1,%2,%3};"
        : "+f"(c[0]), "+f"(c[1]), "+f"(c[2]), "+f"(c[3])
        : "r"(a[0]), "r"(a[1]), "r"(a[2]), "r"(a[3]), "r"(b[0]), "r"(b[1]));
}

// ---------------------------------------------------------------------------
// GEMM: C[z][m][n] = sum_k A[m][k] * B[z][n][k]   (fp16 single-term)
// 128x128 CTA tile, BK=32, 4-stage cp.async pipeline, 2 CTAs/SM.
// 128 threads = 4 warps (2m x 2n), 64x64 per warp.
// PASS==0: A = g_A16 (shared);      C -> g_w16T fp16 transposed + rn partials
// PASS==1: A = g_A2[z] (per-batch); C -> outp fp32 [b][c][n]
// ---------------------------------------------------------------------------
#define TILE 128
#define BK 32
#define T_TILES 24                 // 768 / 32
#define ROWB 80                    // padded row bytes (32*2 data + 16 pad)
#define ABYTES (TILE * ROWB)       // 10240 per array
#define STAGE_BYTES (2 * ABYTES)   // A, B
#define STAGES 4
#define SMEM_GEMM (STAGES * STAGE_BYTES)   // 81920 -> 2 CTAs/SM (164KB)
#define TSTRIDE 136                // staging stride (halfs); 272B rows, 16B aligned

template <int PASS>
__global__ void __launch_bounds__(128, 2)
gemm_mma_kernel(float* __restrict__ outp)
{
    extern __shared__ char smem[];
    const uint32_t su = smem_to_u32(smem);
    const int tid = threadIdx.x;
    const int wid = tid >> 5, lid = tid & 31;
    const int nBlk = blockIdx.x, mBlk = blockIdx.y, z = blockIdx.z;

    const __half* baseA = (PASS ? (g_A2 + (size_t)z * CDIM * CDIM) : g_A16)
                          + (size_t)mBlk * TILE * CDIM;
    const __half* baseB = g_B16 + ((size_t)z * NTOK + (size_t)nBlk * TILE) * CDIM;

    auto prefetch = [&](int t, int s) {
        const uint32_t sb = su + s * STAGE_BYTES;
        const int koff = t * BK;
        #pragma unroll
        for (int q = 0; q < 8; q++) {
            const int i   = q * 128 + tid;     // 0..1023
            const int arr = i >> 9;            // 0: A, 1: B
            const int idx = i & 511;
            const int row = idx >> 2, col = idx & 3;
            const __half* src = (arr ? baseB : baseA) + (size_t)row * CDIM + koff + col * 8;
            const uint32_t dst = sb + arr * ABYTES + row * ROWB + col * 16;
            CP_ASYNC16(dst, src);
        }
        CP_COMMIT();
    };

    prefetch(0, 0); prefetch(1, 1); prefetch(2, 2);   // STAGES-1 in flight

    // warp tiling: 2 (m) x 2 (n), 64x64 per warp
    const int mbase = (wid >> 1) * 64;
    const int nbase = (wid & 1) * 64;
    const int li = lid >> 3, lj = lid & 7;
    const uint32_t aoff = (uint32_t)(mbase + (li & 1) * 8 + lj) * ROWB + (li >> 1) * 16;
    const uint32_t boff = (uint32_t)(nbase + (li >> 1) * 8 + lj) * ROWB + (li & 1) * 16;

    float acc[4][8][4];
    #pragma unroll
    for (int mi = 0; mi < 4; mi++)
        #pragma unroll
        for (int ni = 0; ni < 8; ni++)
            #pragma unroll
            for (int r = 0; r < 4; r++) acc[mi][ni][r] = 0.f;

    for (int t = 0; t < T_TILES; t++) {
        const int s = t % STAGES;
        cp_wait_group<STAGES - 2>();   // tile t resident
        __syncthreads();               // also releases stage (t-1)%S for overwrite

        if (t + STAGES - 1 < T_TILES) prefetch(t + STAGES - 1, (t + STAGES - 1) % STAGES);
        else CP_COMMIT();              // empty group keeps wait accounting exact

        const uint32_t sA = su + s * STAGE_BYTES;
        const uint32_t sB = sA + ABYTES;

        #pragma unroll
        for (int ks = 0; ks < 2; ks++) {
            const uint32_t ko = ks * 32;   // k-offset bytes (16 fp16)
            uint32_t ar[4][4], br[8][2];
            #pragma unroll
            for (int mi = 0; mi < 4; mi++)
                LDSM4(ar[mi][0], ar[mi][1], ar[mi][2], ar[mi][3],
                      sA + aoff + mi * (16 * ROWB) + ko);
            #pragma unroll
            for (int bi = 0; bi < 4; bi++) {
                uint32_t r0, r1, r2, r3;
                LDSM4(r0, r1, r2, r3, sB + boff + bi * (16 * ROWB) + ko);
                br[bi * 2][0] = r0; br[bi * 2][1] = r1;
                br[bi * 2 + 1][0] = r2; br[bi * 2 + 1][1] = r3;
            }
            #pragma unroll
            for (int mi = 0; mi < 4; mi++)
                #pragma unroll
                for (int ni = 0; ni < 8; ni++)
                    mma16816h(acc[mi][ni], ar[mi], br[ni]);
        }
    }

    if constexpr (PASS == 1) {
        // fp32 write, [b][c][n]
        float* Cb = outp + (size_t)z * CDIM * NTOK;
        const int gr0 = mBlk * TILE + mbase + (lid >> 2);
        const int gc0 = nBlk * TILE + nbase + (lid & 3) * 2;
        #pragma unroll
        for (int mi = 0; mi < 4; mi++)
            #pragma unroll
            for (int ni = 0; ni < 8; ni++) {
                float* p = Cb + (size_t)(gr0 + mi * 16) * NTOK + gc0 + ni * 8;
                *(float2*)p = make_float2(acc[mi][ni][0], acc[mi][ni][1]);
                *(float2*)(p + (size_t)8 * NTOK) = make_float2(acc[mi][ni][2], acc[mi][ni][3]);
            }
    } else {
        // fp16 transposed write via smem staging + rownorm partials
        __syncthreads();   // mainloop smem reads done (tail groups are empty)
        __half* st = (__half*)smem;                          // [128 n][TSTRIDE m]
        float*  sp = (float*)(smem + 128 * TSTRIDE * 2);     // 256 floats

        const int r0 = mbase + (lid >> 2);
        const int c0 = nbase + (lid & 3) * 2;
        #pragma unroll
        for (int mi = 0; mi < 4; mi++)
            #pragma unroll
            for (int ni = 0; ni < 8; ni++) {
                const int r = r0 + mi * 16, c = c0 + ni * 8;
                st[c * TSTRIDE + r]           = __float2half(acc[mi][ni][0]);
                st[(c + 1) * TSTRIDE + r]     = __float2half(acc[mi][ni][1]);
                st[c * TSTRIDE + r + 8]       = __float2half(acc[mi][ni][2]);
                st[(c + 1) * TSTRIDE + r + 8] = __float2half(acc[mi][ni][3]);
            }

        // deterministic per-row sumsq partials: quad-shuffle + 2-warp smem reduce
        #pragma unroll
        for (int mi = 0; mi < 4; mi++)
            #pragma unroll
            for (int sub = 0; sub < 2; sub++) {
                float v = 0.f;
                #pragma unroll
                for (int ni = 0; ni < 8; ni++) {
                    float a0 = acc[mi][ni][sub * 2 + 0];
                    float a1 = acc[mi][ni][sub * 2 + 1];
                    v += a0 * a0 + a1 * a1;
                }
                v += __shfl_xor_sync(0xffffffffu, v, 1);
                v += __shfl_xor_sync(0xffffffffu, v, 2);
                if ((lid & 3) == 0) {
                    int rl = mbase + mi * 16 + sub * 8 + (lid >> 2);
                    sp[rl * 2 + (wid & 1)] = v;
                }
            }
        __syncthreads();

        // coalesced global write: 16 uint4 chunks per n-row, threads sweep rows
        #pragma unroll
        for (int it = 0; it < 16; it++) {
            const int idx = it * 128 + tid;       // 0..2047
            const int n = idx >> 4, cch = idx & 15;
            uint4 v = *(const uint4*)(st + n * TSTRIDE + cch * 8);
            *(uint4*)(g_w16T + ((size_t)z * NTOK + nBlk * TILE + n) * CDIM
                      + mBlk * TILE + cch * 8) = v;
        }
        {
            float v = sp[tid * 2] + sp[tid * 2 + 1];
            g_rnPart[((size_t)z * CDIM + mBlk * TILE + tid) * 32 + nBlk] = v;
        }
    }
}

// ---------------------------------------------------------------------------
// rownorm partial reduce: inv2 = 1/max(sqrt(sum),1e-12)^2
// ---------------------------------------------------------------------------
__global__ void rownorm_reduce_kernel() {
    int row = blockIdx.x * 256 + threadIdx.x;   // 0 .. BATCH*CDIM-1
    const float4* p = (const float4*)(g_rnPart + (size_t)row * 32);
    float s = 0.f;
    #pragma unroll
    for (int i = 0; i < 8; i++) { float4 v = p[i]; s += v.x + v.y + v.z + v.w; }
    float nrm = fmaxf(sqrtf(s), 1e-12f);
    g_inv2[row] = 1.f / (nrm * nrm);
}

// ---------------------------------------------------------------------------
// Fused stats off transposed fp16 w: per 32-token tile, one read ->
//   logits -> head-softmax Pi -> Pi-sum partials -> dots partials
//   -> write B16 = -w * Pi  (attn folded into GEMM2's A operand later)
// ---------------------------------------------------------------------------
#define FS_STRIDE 770
#define SMEM_FS (32 * FS_STRIDE * 2 + CDIM * 4 + 32 * HEADS * 4 + HEADS * 32 * 4)

__global__ void __launch_bounds__(256)
fusedstats_kernel(const float* __restrict__ temp) {
    extern __shared__ char fsmem[];
    __half* s_w     = (__half*)fsmem;                         // [32][770]
    float*  s_inv2  = (float*)(fsmem + 32 * FS_STRIDE * 2);   // [768]
    float*  s_logit = s_inv2 + CDIM;                          // [32][12]
    float*  s_Pi    = s_logit + 32 * HEADS;                   // [12][32]
    const int b = blockIdx.y, blk = blockIdx.x, n0 = blk * 32, tid = threadIdx.x;
    const __half* wb = g_w16T + ((size_t)b * NTOK + n0) * CDIM;

    for (int i = tid; i < 32 * 96; i += 256) {
        int t = i / 96, c8 = (i % 96) * 8;
        uint4 v = *(const uint4*)(wb + (size_t)t * CDIM + c8);
        uint32_t* vv = (uint32_t*)&v;
        uint32_t* dst = (uint32_t*)(s_w + t * FS_STRIDE + c8);
        dst[0] = vv[0]; dst[1] = vv[1]; dst[2] = vv[2]; dst[3] = vv[3];
    }
    for (int i = tid; i < CDIM; i += 256) s_inv2[i] = g_inv2[b * CDIM + i];
    __syncthreads();

    for (int p = tid; p < 32 * HEADS; p += 256) {
        int t = p & 31, h = p >> 5;
        const __half* wr = s_w + t * FS_STRIDE + h * DHEAD;
        const float* iv = s_inv2 + h * DHEAD;
        float a = 0.f;
        #pragma unroll 16
        for (int d = 0; d < DHEAD; d++) {
            float v = __half2float(wr[d]);
            a = fmaf(v * v, iv[d], a);
        }
        s_logit[t * HEADS + h] = a * temp[h];
    }
    __syncthreads();

    if (tid < 32) {
        int t = tid;
        float m = s_logit[t * HEADS];
        #pragma unroll
        for (int h = 1; h < HEADS; h++) m = fmaxf(m, s_logit[t * HEADS + h]);
        float s = 0.f, e[HEADS];
        #pragma unroll
        for (int h = 0; h < HEADS; h++) { e[h] = expf(s_logit[t * HEADS + h] - m); s += e[h]; }
        float inv = 1.f / s;
        #pragma unroll
        for (int h = 0; h < HEADS; h++) s_Pi[h * 32 + t] = e[h] * inv;
    }
    __syncthreads();

    if (tid < HEADS) {   // Pi-sum partials (deterministic fixed order)
        float s = 0.f;
        #pragma unroll 8
        for (int t = 0; t < 32; t++) s += s_Pi[tid * 32 + t];
        g_PiP[((size_t)b * 128 + blk) * HEADS + tid] = s;
    }

    // dots partials
    for (int co = tid; co < CDIM; co += 256) {
        int h = co >> 6;
        const float* pr = s_Pi + h * 32;
        float s = 0.f;
        #pragma unroll 8
        for (int t = 0; t < 32; t++) {
            float v = __half2float(s_w[t * FS_STRIDE + co]);
            s = fmaf(v * v, pr[t], s);
        }
        g_dotsP[((size_t)b * 128 + blk) * CDIM + co] = s;
    }

    // B16 = -w * Pi  (coalesced uint4 writes)
    __half* ob = g_B16 + ((size_t)b * NTOK + n0) * CDIM;
    for (int i = tid; i < 32 * 96; i += 256) {
        int t = i / 96, c8 = (i % 96) * 8;
        float pi = -s_Pi[(c8 >> 6) * 32 + t];
        uint4 v;
        __half2* hv = (__half2*)&v;
        const __half2* sv = (const __half2*)(s_w + t * FS_STRIDE + c8);
        #pragma unroll
        for (int j = 0; j < 4; j++) {
            float2 f = __half22float2(sv[j]);
            hv[j] = __floats2half2_rn(f.x * pi, f.y * pi);
        }
        *(uint4*)(ob + (size_t)t * CDIM + c8) = v;
    }
}

// ---------------------------------------------------------------------------
// Pi-sum reduce + dots reduce -> attn
// ---------------------------------------------------------------------------
__global__ void pisum_reduce_kernel() {   // 1 block, 192 threads
    int b = threadIdx.x / HEADS, h = threadIdx.x % HEADS;
    float s = 0.f;
    for (int blk = 0; blk < 128; blk++)
        s += g_PiP[((size_t)b * 128 + blk) * HEADS + h];
    g_PiSum[threadIdx.x] = s;
}

__global__ void dots_reduce_kernel() {   // grid (CDIM/256, BATCH)
    int b = blockIdx.y, co = blockIdx.x * 256 + threadIdx.x;
    int h = co >> 6;
    const float* p = g_dotsP + (size_t)b * 128 * CDIM + co;
    float s = 0.f;
    for (int blk = 0; blk < 128; blk++) s += p[(size_t)blk * CDIM];
    float dots = s / (g_PiSum[b * HEADS + h] + 1e-8f);
    g_attn[b * CDIM + co] = 1.f / (1.f + dots);
}

// ---------------------------------------------------------------------------
// A2[b][m][c] = fp16(W_out_fp32[m][c] * attn[b][c])   (single rounding)
// ---------------------------------------------------------------------------
__global__ void __launch_bounds__(256)
attnA_kernel(const float* __restrict__ Wo) {
    const int b = blockIdx.y;
    size_t e = ((size_t)blockIdx.x * 256 + threadIdx.x) * 8;   // within [m][c]
    int c = (int)(e % CDIM);
    const float* at = g_attn + b * CDIM + c;
    const float4* wp = (const float4*)(Wo + e);
    float4 w0 = wp[0], w1 = wp[1];
    uint4 v;
    __half2* hv = (__half2*)&v;
    hv[0] = __floats2half2_rn(w0.x * at[0], w0.y * at[1]);
    hv[1] = __floats2half2_rn(w0.z * at[2], w0.w * at[3]);
    hv[2] = __floats2half2_rn(w1.x * at[4], w1.y * at[5]);
    hv[3] = __floats2half2_rn(w1.z * at[6], w1.w * at[7]);
    *(uint4*)(g_A2 + (size_t)b * CDIM * CDIM + e) = v;
}

// ---------------------------------------------------------------------------
// Convert W_qkv to fp16 (K-major layout preserved)
// ---------------------------------------------------------------------------
__global__ void convW_kernel(const float* __restrict__ Wq) {
    int i = blockIdx.x * 256 + threadIdx.x;
    if (i >= CDIM * CDIM) return;
    g_A16[i] = __float2half(Wq[i]);
}

// ---------------------------------------------------------------------------
// Transpose x: [b][c][n] fp32 -> [b][n][c] fp16 (GEMM1 operand)
// ---------------------------------------------------------------------------
__global__ void xT_kernel(const float* __restrict__ in) {
    __shared__ float tile[32][33];
    const int b = blockIdx.z;
    const int n0 = blockIdx.x * 32, c0 = blockIdx.y * 32;
    const int tx = threadIdx.x, ty = threadIdx.y;
    const float* src = in + (size_t)b * CDIM * NTOK;
    #pragma unroll
    for (int r = 0; r < 4; r++) {
        int c = c0 + ty + r * 8;
        tile[ty + r * 8][tx] = src[(size_t)c * NTOK + n0 + tx];
    }
    __syncthreads();
    const size_t obase = ((size_t)b * NTOK + n0) * CDIM + c0;
    #pragma unroll
    for (int r = 0; r < 4; r++) {
        int nn = ty + r * 8;
        g_B16[obase + (size_t)nn * CDIM + tx] = __float2half(tile[tx][nn]);
    }
}

// ---------------------------------------------------------------------------
// launch
// ---------------------------------------------------------------------------
extern "C" void kernel_launch(void* const* d_in, const int* in_sizes, int n_in,
                              void* d_out, int out_size) {
    (void)in_sizes; (void)n_in; (void)out_size;
    const float* x     = (const float*)d_in[0];
    const float* W_qkv = (const float*)d_in[1];
    const float* W_out = (const float*)d_in[2];
    const float* temp  = (const float*)d_in[3];
    float* out = (float*)d_out;

    cudaFuncSetAttribute(gemm_mma_kernel<0>, cudaFuncAttributeMaxDynamicSharedMemorySize, SMEM_GEMM);
    cudaFuncSetAttribute(gemm_mma_kernel<1>, cudaFuncAttributeMaxDynamicSharedMemorySize, SMEM_GEMM);
    cudaFuncSetAttribute(fusedstats_kernel, cudaFuncAttributeMaxDynamicSharedMemorySize, SMEM_FS);

    dim3 gemmGrid(NTOK / TILE, CDIM / TILE, BATCH);     // (32, 6, 16)
    dim3 trGrid(NTOK / 32, CDIM / 32, BATCH);
    dim3 trBlk(32, 8);

    convW_kernel<<<(CDIM * CDIM + 255) / 256, 256>>>(W_qkv);
    xT_kernel<<<trGrid, trBlk>>>(x);
    gemm_mma_kernel<0><<<gemmGrid, 128, SMEM_GEMM>>>(nullptr);
    rownorm_reduce_kernel<<<BATCH * CDIM / 256, 256>>>();
    fusedstats_kernel<<<dim3(NTOK / 32, BATCH), 256, SMEM_FS>>>(temp);
    pisum_reduce_kernel<<<1, BATCH * HEADS>>>();
    dots_reduce_kernel<<<dim3(CDIM / 256, BATCH), 256>>>();
    attnA_kernel<<<dim3(CDIM * CDIM / 8 / 256, BATCH), 256>>>(W_out);
    gemm_mma_kernel<1><<<gemmGrid, 128, SMEM_GEMM>>>(out);
}

// round 17
// speedup vs baseline: 1.5095x; 1.5095x over previous
#include <cuda_runtime.h>
#include <cuda_fp16.h>
#include <cstdint>

// Problem constants
#define BATCH 16
#define CDIM  768
#define NTOK  4096
#define HEADS 12
#define DHEAD 64

// ---------------------------------------------------------------------------
// Scratch (__device__ globals; no cudaMalloc allowed)
// ---------------------------------------------------------------------------
__device__ __half g_w16T[(size_t)BATCH * NTOK * CDIM];      // w fp16, [b][n][c]
__device__ float g_inv2[BATCH * CDIM];
__device__ float g_attn[BATCH * CDIM];
__device__ float g_PiSum[BATCH * HEADS];
__device__ float g_rnPart[(size_t)BATCH * CDIM * 32];       // rownorm partials [row][nBlk]
__device__ float g_dotsP[(size_t)BATCH * 128 * CDIM];       // dots partials [b][blk][co]
__device__ float g_PiP[(size_t)BATCH * 128 * HEADS];        // Pi-sum partials [b][blk][h]
__device__ __half g_A16[CDIM * CDIM];                       // W_qkv fp16, [m][k]
__device__ __half g_A2[(size_t)BATCH * CDIM * CDIM];        // W_out*attn fp16, [b][m][k]
__device__ __half g_B16[(size_t)BATCH * NTOK * CDIM];       // B operand fp16, [b][n][k]

// ---------------------------------------------------------------------------
// PTX helpers (baseline sm_80+ features only: cp.async, ldmatrix, mma.sync)
// ---------------------------------------------------------------------------
__device__ __forceinline__ uint32_t smem_to_u32(const void* p) {
    uint32_t a;
    asm("{ .reg .u64 t; cvta.to.shared.u64 t, %1; cvt.u32.u64 %0, t; }" : "=r"(a) : "l"(p));
    return a;
}
#define CP_ASYNC16(dst, src) asm volatile( \
    "cp.async.cg.shared.global [%0], [%1], 16;" :: "r"(dst), "l"(src) : "memory")
#define CP_COMMIT() asm volatile("cp.async.commit_group;" ::: "memory")
template <int N>
__device__ __forceinline__ void cp_wait_group() {
    asm volatile("cp.async.wait_group %0;" :: "n"(N) : "memory");
}
#define LDSM4(r0, r1, r2, r3, addr) asm volatile( \
    "ldmatrix.sync.aligned.m8n8.x4.shared.b16 {%0,%1,%2,%3}, [%4];" \
    : "=r"(r0), "=r"(r1), "=r"(r2), "=r"(r3) : "r"(addr))

__device__ __forceinline__ void mma16816h(float* c, const uint32_t* a, const uint32_t* b) {
    asm volatile(
        "mma.sync.aligned.m16n8k16.row.col.f32.f16.f16.f32 "
        "{%0,%1,%2,%3}, {%4,%5,%6,%7}, {%8,%9}, {%0,%1,%2,%3};"
        : "+f"(c[0]), "+f"(c[1]), "+f"(c[2]), "+f"(c[3])
        : "r"(a[0]), "r"(a[1]), "r"(a[2]), "r"(a[3]), "r"(b[0]), "r"(b[1]));
}

// ---------------------------------------------------------------------------
// GEMM: C[z][m][n] = sum_k A[m][k] * B[z][n][k]   (fp16 single-term)
// 128x128 CTA tile, BK=32, 4-stage cp.async pipeline, 2 CTAs/SM.
// 128 threads = 4 warps (2m x 2n), 64x64 per warp.
// PASS==0: A = g_A16 (shared);      C -> g_w16T fp16 transposed + rn partials
// PASS==1: A = g_A2[z] (per-batch); C -> outp fp32 [b][c][n]
// ---------------------------------------------------------------------------
#define TILE 128
#define BK 32
#define T_TILES 24                 // 768 / 32
#define ROWB 80                    // padded row bytes (32*2 data + 16 pad)
#define ABYTES (TILE * ROWB)       // 10240 per array
#define STAGE_BYTES (2 * ABYTES)   // A, B
#define STAGES 4
#define SMEM_GEMM (STAGES * STAGE_BYTES)   // 81920 -> 2 CTAs/SM (164KB)
#define TSTRIDE 136                // staging stride (halfs); 272B rows, 16B aligned

template <int PASS>
__global__ void __launch_bounds__(128, 2)
gemm_mma_kernel(float* __restrict__ outp)
{
    extern __shared__ char smem[];
    const uint32_t su = smem_to_u32(smem);
    const int tid = threadIdx.x;
    const int wid = tid >> 5, lid = tid & 31;
    const int nBlk = blockIdx.x, mBlk = blockIdx.y, z = blockIdx.z;

    const __half* baseA = (PASS ? (g_A2 + (size_t)z * CDIM * CDIM) : g_A16)
                          + (size_t)mBlk * TILE * CDIM;
    const __half* baseB = g_B16 + ((size_t)z * NTOK + (size_t)nBlk * TILE) * CDIM;

    auto prefetch = [&](int t, int s) {
        const uint32_t sb = su + s * STAGE_BYTES;
        const int koff = t * BK;
        #pragma unroll
        for (int q = 0; q < 8; q++) {
            const int i   = q * 128 + tid;     // 0..1023
            const int arr = i >> 9;            // 0: A, 1: B
            const int idx = i & 511;
            const int row = idx >> 2, col = idx & 3;
            const __half* src = (arr ? baseB : baseA) + (size_t)row * CDIM + koff + col * 8;
            const uint32_t dst = sb + arr * ABYTES + row * ROWB + col * 16;
            CP_ASYNC16(dst, src);
        }
        CP_COMMIT();
    };

    prefetch(0, 0); prefetch(1, 1); prefetch(2, 2);   // STAGES-1 in flight

    // warp tiling: 2 (m) x 2 (n), 64x64 per warp
    const int mbase = (wid >> 1) * 64;
    const int nbase = (wid & 1) * 64;
    const int li = lid >> 3, lj = lid & 7;
    const uint32_t aoff = (uint32_t)(mbase + (li & 1) * 8 + lj) * ROWB + (li >> 1) * 16;
    const uint32_t boff = (uint32_t)(nbase + (li >> 1) * 8 + lj) * ROWB + (li & 1) * 16;

    float acc[4][8][4];
    #pragma unroll
    for (int mi = 0; mi < 4; mi++)
        #pragma unroll
        for (int ni = 0; ni < 8; ni++)
            #pragma unroll
            for (int r = 0; r < 4; r++) acc[mi][ni][r] = 0.f;

    for (int t = 0; t < T_TILES; t++) {
        const int s = t % STAGES;
        cp_wait_group<STAGES - 2>();   // tile t resident
        __syncthreads();               // also releases stage (t-1)%S for overwrite

        if (t + STAGES - 1 < T_TILES) prefetch(t + STAGES - 1, (t + STAGES - 1) % STAGES);
        else CP_COMMIT();              // empty group keeps wait accounting exact

        const uint32_t sA = su + s * STAGE_BYTES;
        const uint32_t sB = sA + ABYTES;

        #pragma unroll
        for (int ks = 0; ks < 2; ks++) {
            const uint32_t ko = ks * 32;   // k-offset bytes (16 fp16)
            uint32_t ar[4][4], br[8][2];
            #pragma unroll
            for (int mi = 0; mi < 4; mi++)
                LDSM4(ar[mi][0], ar[mi][1], ar[mi][2], ar[mi][3],
                      sA + aoff + mi * (16 * ROWB) + ko);
            #pragma unroll
            for (int bi = 0; bi < 4; bi++) {
                uint32_t r0, r1, r2, r3;
                LDSM4(r0, r1, r2, r3, sB + boff + bi * (16 * ROWB) + ko);
                br[bi * 2][0] = r0; br[bi * 2][1] = r1;
                br[bi * 2 + 1][0] = r2; br[bi * 2 + 1][1] = r3;
            }
            #pragma unroll
            for (int mi = 0; mi < 4; mi++)
                #pragma unroll
                for (int ni = 0; ni < 8; ni++)
                    mma16816h(acc[mi][ni], ar[mi], br[ni]);
        }
    }

    if constexpr (PASS == 1) {
        // fp32 write, [b][c][n]
        float* Cb = outp + (size_t)z * CDIM * NTOK;
        const int gr0 = mBlk * TILE + mbase + (lid >> 2);
        const int gc0 = nBlk * TILE + nbase + (lid & 3) * 2;
        #pragma unroll
        for (int mi = 0; mi < 4; mi++)
            #pragma unroll
            for (int ni = 0; ni < 8; ni++) {
                float* p = Cb + (size_t)(gr0 + mi * 16) * NTOK + gc0 + ni * 8;
                *(float2*)p = make_float2(acc[mi][ni][0], acc[mi][ni][1]);
                *(float2*)(p + (size_t)8 * NTOK) = make_float2(acc[mi][ni][2], acc[mi][ni][3]);
            }
    } else {
        // fp16 transposed write via smem staging + rownorm partials
        __syncthreads();   // mainloop smem reads done (tail groups are empty)
        __half* st = (__half*)smem;                          // [128 n][TSTRIDE m]
        float*  sp = (float*)(smem + 128 * TSTRIDE * 2);     // 256 floats

        const int r0 = mbase + (lid >> 2);
        const int c0 = nbase + (lid & 3) * 2;
        #pragma unroll
        for (int mi = 0; mi < 4; mi++)
            #pragma unroll
            for (int ni = 0; ni < 8; ni++) {
                const int r = r0 + mi * 16, c = c0 + ni * 8;
                st[c * TSTRIDE + r]           = __float2half(acc[mi][ni][0]);
                st[(c + 1) * TSTRIDE + r]     = __float2half(acc[mi][ni][1]);
                st[c * TSTRIDE + r + 8]       = __float2half(acc[mi][ni][2]);
                st[(c + 1) * TSTRIDE + r + 8] = __float2half(acc[mi][ni][3]);
            }

        // deterministic per-row sumsq partials: quad-shuffle + 2-warp smem reduce
        #pragma unroll
        for (int mi = 0; mi < 4; mi++)
            #pragma unroll
            for (int sub = 0; sub < 2; sub++) {
                float v = 0.f;
                #pragma unroll
                for (int ni = 0; ni < 8; ni++) {
                    float a0 = acc[mi][ni][sub * 2 + 0];
                    float a1 = acc[mi][ni][sub * 2 + 1];
                    v += a0 * a0 + a1 * a1;
                }
                v += __shfl_xor_sync(0xffffffffu, v, 1);
                v += __shfl_xor_sync(0xffffffffu, v, 2);
                if ((lid & 3) == 0) {
                    int rl = mbase + mi * 16 + sub * 8 + (lid >> 2);
                    sp[rl * 2 + (wid & 1)] = v;
                }
            }
        __syncthreads();

        // coalesced global write: 16 uint4 chunks per n-row, threads sweep rows
        #pragma unroll
        for (int it = 0; it < 16; it++) {
            const int idx = it * 128 + tid;       // 0..2047
            const int n = idx >> 4, cch = idx & 15;
            uint4 v = *(const uint4*)(st + n * TSTRIDE + cch * 8);
            *(uint4*)(g_w16T + ((size_t)z * NTOK + nBlk * TILE + n) * CDIM
                      + mBlk * TILE + cch * 8) = v;
        }
        {
            float v = sp[tid * 2] + sp[tid * 2 + 1];
            g_rnPart[((size_t)z * CDIM + mBlk * TILE + tid) * 32 + nBlk] = v;
        }
    }
}

// ---------------------------------------------------------------------------
// rownorm partial reduce: inv2 = 1/max(sqrt(sum),1e-12)^2
// ---------------------------------------------------------------------------
__global__ void rownorm_reduce_kernel() {
    int row = blockIdx.x * 256 + threadIdx.x;   // 0 .. BATCH*CDIM-1
    const float4* p = (const float4*)(g_rnPart + (size_t)row * 32);
    float s = 0.f;
    #pragma unroll
    for (int i = 0; i < 8; i++) { float4 v = p[i]; s += v.x + v.y + v.z + v.w; }
    float nrm = fmaxf(sqrtf(s), 1e-12f);
    g_inv2[row] = 1.f / (nrm * nrm);
}

// ---------------------------------------------------------------------------
// Fused stats off transposed fp16 w: per 32-token tile, one read ->
//   logits -> head-softmax Pi -> Pi-sum partials -> dots partials
//   -> write B16 = -w * Pi  (attn folded into GEMM2's A operand later)
// ---------------------------------------------------------------------------
#define FS_STRIDE 770
#define SMEM_FS (32 * FS_STRIDE * 2 + CDIM * 4 + 32 * HEADS * 4 + HEADS * 32 * 4)

__global__ void __launch_bounds__(256)
fusedstats_kernel(const float* __restrict__ temp) {
    extern __shared__ char fsmem[];
    __half* s_w     = (__half*)fsmem;                         // [32][770]
    float*  s_inv2  = (float*)(fsmem + 32 * FS_STRIDE * 2);   // [768]
    float*  s_logit = s_inv2 + CDIM;                          // [32][12]
    float*  s_Pi    = s_logit + 32 * HEADS;                   // [12][32]
    const int b = blockIdx.y, blk = blockIdx.x, n0 = blk * 32, tid = threadIdx.x;
    const __half* wb = g_w16T + ((size_t)b * NTOK + n0) * CDIM;

    for (int i = tid; i < 32 * 96; i += 256) {
        int t = i / 96, c8 = (i % 96) * 8;
        uint4 v = *(const uint4*)(wb + (size_t)t * CDIM + c8);
        uint32_t* vv = (uint32_t*)&v;
        uint32_t* dst = (uint32_t*)(s_w + t * FS_STRIDE + c8);
        dst[0] = vv[0]; dst[1] = vv[1]; dst[2] = vv[2]; dst[3] = vv[3];
    }
    for (int i = tid; i < CDIM; i += 256) s_inv2[i] = g_inv2[b * CDIM + i];
    __syncthreads();

    for (int p = tid; p < 32 * HEADS; p += 256) {
        int t = p & 31, h = p >> 5;
        const __half* wr = s_w + t * FS_STRIDE + h * DHEAD;
        const float* iv = s_inv2 + h * DHEAD;
        float a = 0.f;
        #pragma unroll 16
        for (int d = 0; d < DHEAD; d++) {
            float v = __half2float(wr[d]);
            a = fmaf(v * v, iv[d], a);
        }
        s_logit[t * HEADS + h] = a * temp[h];
    }
    __syncthreads();

    if (tid < 32) {
        int t = tid;
        float m = s_logit[t * HEADS];
        #pragma unroll
        for (int h = 1; h < HEADS; h++) m = fmaxf(m, s_logit[t * HEADS + h]);
        float s = 0.f, e[HEADS];
        #pragma unroll
        for (int h = 0; h < HEADS; h++) { e[h] = expf(s_logit[t * HEADS + h] - m); s += e[h]; }
        float inv = 1.f / s;
        #pragma unroll
        for (int h = 0; h < HEADS; h++) s_Pi[h * 32 + t] = e[h] * inv;
    }
    __syncthreads();

    if (tid < HEADS) {   // Pi-sum partials (deterministic fixed order)
        float s = 0.f;
        #pragma unroll 8
        for (int t = 0; t < 32; t++) s += s_Pi[tid * 32 + t];
        g_PiP[((size_t)b * 128 + blk) * HEADS + tid] = s;
    }

    // dots partials
    for (int co = tid; co < CDIM; co += 256) {
        int h = co >> 6;
        const float* pr = s_Pi + h * 32;
        float s = 0.f;
        #pragma unroll 8
        for (int t = 0; t < 32; t++) {
            float v = __half2float(s_w[t * FS_STRIDE + co]);
            s = fmaf(v * v, pr[t], s);
        }
        g_dotsP[((size_t)b * 128 + blk) * CDIM + co] = s;
    }

    // B16 = -w * Pi  (coalesced uint4 writes)
    __half* ob = g_B16 + ((size_t)b * NTOK + n0) * CDIM;
    for (int i = tid; i < 32 * 96; i += 256) {
        int t = i / 96, c8 = (i % 96) * 8;
        float pi = -s_Pi[(c8 >> 6) * 32 + t];
        uint4 v;
        __half2* hv = (__half2*)&v;
        const __half2* sv = (const __half2*)(s_w + t * FS_STRIDE + c8);
        #pragma unroll
        for (int j = 0; j < 4; j++) {
            float2 f = __half22float2(sv[j]);
            hv[j] = __floats2half2_rn(f.x * pi, f.y * pi);
        }
        *(uint4*)(ob + (size_t)t * CDIM + c8) = v;
    }
}

// ---------------------------------------------------------------------------
// Pi-sum reduce + dots reduce -> attn
// ---------------------------------------------------------------------------
__global__ void pisum_reduce_kernel() {   // 1 block, 192 threads
    int b = threadIdx.x / HEADS, h = threadIdx.x % HEADS;
    float s = 0.f;
    for (int blk = 0; blk < 128; blk++)
        s += g_PiP[((size_t)b * 128 + blk) * HEADS + h];
    g_PiSum[threadIdx.x] = s;
}

__global__ void dots_reduce_kernel() {   // grid (CDIM/256, BATCH)
    int b = blockIdx.y, co = blockIdx.x * 256 + threadIdx.x;
    int h = co >> 6;
    const float* p = g_dotsP + (size_t)b * 128 * CDIM + co;
    float s = 0.f;
    for (int blk = 0; blk < 128; blk++) s += p[(size_t)blk * CDIM];
    float dots = s / (g_PiSum[b * HEADS + h] + 1e-8f);
    g_attn[b * CDIM + co] = 1.f / (1.f + dots);
}

// ---------------------------------------------------------------------------
// A2[b][m][c] = fp16(W_out_fp32[m][c] * attn[b][c])   (single rounding)
// ---------------------------------------------------------------------------
__global__ void __launch_bounds__(256)
attnA_kernel(const float* __restrict__ Wo) {
    const int b = blockIdx.y;
    size_t e = ((size_t)blockIdx.x * 256 + threadIdx.x) * 8;   // within [m][c]
    int c = (int)(e % CDIM);
    const float* at = g_attn + b * CDIM + c;
    const float4* wp = (const float4*)(Wo + e);
    float4 w0 = wp[0], w1 = wp[1];
    uint4 v;
    __half2* hv = (__half2*)&v;
    hv[0] = __floats2half2_rn(w0.x * at[0], w0.y * at[1]);
    hv[1] = __floats2half2_rn(w0.z * at[2], w0.w * at[3]);
    hv[2] = __floats2half2_rn(w1.x * at[4], w1.y * at[5]);
    hv[3] = __floats2half2_rn(w1.z * at[6], w1.w * at[7]);
    *(uint4*)(g_A2 + (size_t)b * CDIM * CDIM + e) = v;
}

// ---------------------------------------------------------------------------
// Convert W_qkv to fp16 (K-major layout preserved)
// ---------------------------------------------------------------------------
__global__ void convW_kernel(const float* __restrict__ Wq) {
    int i = blockIdx.x * 256 + threadIdx.x;
    if (i >= CDIM * CDIM) return;
    g_A16[i] = __float2half(Wq[i]);
}

// ---------------------------------------------------------------------------
// Transpose x: [b][c][n] fp32 -> [b][n][c] fp16 (GEMM1 operand)
// ---------------------------------------------------------------------------
__global__ void xT_kernel(const float* __restrict__ in) {
    __shared__ float tile[32][33];
    const int b = blockIdx.z;
    const int n0 = blockIdx.x * 32, c0 = blockIdx.y * 32;
    const int tx = threadIdx.x, ty = threadIdx.y;
    const float* src = in + (size_t)b * CDIM * NTOK;
    #pragma unroll
    for (int r = 0; r < 4; r++) {
        int c = c0 + ty + r * 8;
        tile[ty + r * 8][tx] = src[(size_t)c * NTOK + n0 + tx];
    }
    __syncthreads();
    const size_t obase = ((size_t)b * NTOK + n0) * CDIM + c0;
    #pragma unroll
    for (int r = 0; r < 4; r++) {
        int nn = ty + r * 8;
        g_B16[obase + (size_t)nn * CDIM + tx] = __float2half(tile[tx][nn]);
    }
}

// ---------------------------------------------------------------------------
// launch
// ---------------------------------------------------------------------------
extern "C" void kernel_launch(void* const* d_in, const int* in_sizes, int n_in,
                              void* d_out, int out_size) {
    (void)in_sizes; (void)n_in; (void)out_size;
    const float* x     = (const float*)d_in[0];
    const float* W_qkv = (const float*)d_in[1];
    const float* W_out = (const float*)d_in[2];
    const float* temp  = (const float*)d_in[3];
    float* out = (float*)d_out;

    cudaFuncSetAttribute(gemm_mma_kernel<0>, cudaFuncAttributeMaxDynamicSharedMemorySize, SMEM_GEMM);
    cudaFuncSetAttribute(gemm_mma_kernel<1>, cudaFuncAttributeMaxDynamicSharedMemorySize, SMEM_GEMM);
    cudaFuncSetAttribute(fusedstats_kernel, cudaFuncAttributeMaxDynamicSharedMemorySize, SMEM_FS);

    dim3 gemmGrid(NTOK / TILE, CDIM / TILE, BATCH);     // (32, 6, 16)
    dim3 trGrid(NTOK / 32, CDIM / 32, BATCH);
    dim3 trBlk(32, 8);

    convW_kernel<<<(CDIM * CDIM + 255) / 256, 256>>>(W_qkv);
    xT_kernel<<<trGrid, trBlk>>>(x);
    gemm_mma_kernel<0><<<gemmGrid, 128, SMEM_GEMM>>>(nullptr);
    rownorm_reduce_kernel<<<BATCH * CDIM / 256, 256>>>();
    fusedstats_kernel<<<dim3(NTOK / 32, BATCH), 256, SMEM_FS>>>(temp);
    pisum_reduce_kernel<<<1, BATCH * HEADS>>>();
    dots_reduce_kernel<<<dim3(CDIM / 256, BATCH), 256>>>();
    attnA_kernel<<<dim3(CDIM * CDIM / 8 / 256, BATCH), 256>>>(W_out);
    gemm_mma_kernel<1><<<gemmGrid, 128, SMEM_GEMM>>>(out);
}